// round 4
// baseline (speedup 1.0000x reference)
#include <cuda_runtime.h>
#include <cuda_bf16.h>
#include <cstdint>

// Problem constants
#define BB 2
#define MM 4096
#define CC 256
#define HH 64
#define WW 64
#define NLVL 4
#define RAD 4
#define SIDE 9          // 2*RAD+1
#define GRID10 10       // lattice side = SIDE+1
#define OUTCH (NLVL * SIDE * SIDE)   // 324

// Pyramid (pixel-major: [b][level][y][x][c]) in float
// per-batch float offsets
#define OFF0 0
#define OFF1 (4096 * 256)                    // 1048576
#define OFF2 ((4096 + 1024) * 256)           // 1310720
#define OFF3 ((4096 + 1024 + 256) * 256)     // 1376256
#define BSTR ((4096 + 1024 + 256 + 64) * 256) // 1392640 floats per batch
#define PYR_TOTAL (BB * BSTR)                // 2785280 floats

__device__ float4 g_pyr4[PYR_TOTAL / 4];     // 11.1 MB static scratch

// ---------------------------------------------------------------------------
// Kernel A1: transpose fmap2 (b, c, p) -> pyramid level 0 (b, p, c), p = y*W+x
// ---------------------------------------------------------------------------
__global__ void transpose_l0_kernel(const float* __restrict__ fmap2) {
    __shared__ float tile[32][33];
    float* g = reinterpret_cast<float*>(g_pyr4);
    int b  = blockIdx.z;
    int c0 = blockIdx.y * 32;
    int p0 = blockIdx.x * 32;
    const float* in_b = fmap2 + (size_t)b * CC * (HH * WW);
    #pragma unroll
    for (int r = threadIdx.y; r < 32; r += 8)
        tile[r][threadIdx.x] = in_b[(size_t)(c0 + r) * (HH * WW) + p0 + threadIdx.x];
    __syncthreads();
    float* out_b = g + (size_t)b * BSTR;
    #pragma unroll
    for (int r = threadIdx.y; r < 32; r += 8)
        out_b[(size_t)(p0 + r) * CC + c0 + threadIdx.x] = tile[threadIdx.x][r];
}

// ---------------------------------------------------------------------------
// Kernel A2: 2x2 average pool, pixel-major, level (Wi) -> level (Wo = Wi/2)
// ---------------------------------------------------------------------------
__global__ void pool_kernel(int inOff, int outOff, int Wi, int Wo, int total) {
    float* g = reinterpret_cast<float*>(g_pyr4);
    int tid = blockIdx.x * blockDim.x + threadIdx.x;
    if (tid >= total) return;
    int c = tid & (CC - 1);
    int idx = tid >> 8;
    int x = idx % Wo; idx /= Wo;
    int y = idx % Wo; idx /= Wo;
    int b = idx;
    const float* ib = g + (size_t)b * BSTR + inOff;
    float v = 0.25f * (ib[((size_t)(2 * y)     * Wi + 2 * x)     * CC + c] +
                       ib[((size_t)(2 * y)     * Wi + 2 * x + 1) * CC + c] +
                       ib[((size_t)(2 * y + 1) * Wi + 2 * x)     * CC + c] +
                       ib[((size_t)(2 * y + 1) * Wi + 2 * x + 1) * CC + c]);
    g[(size_t)b * BSTR + outOff + ((size_t)y * Wo + x) * CC + c] = v;
}

// ---------------------------------------------------------------------------
// Kernel B: one warp per point. Lane owns 8 channels (2 x float4).
// For each level: 100 lattice dot-products (coalesced 1KB pixel vectors,
// butterfly reduce), then bilinear-combine into 81 outputs.
// ---------------------------------------------------------------------------
__global__ void __launch_bounds__(256, 8)
sample_kernel(const float* __restrict__ fmap1,
              const float* __restrict__ cents,
              float* __restrict__ out) {
    __shared__ float Cs[8][104];
    const int warp = threadIdx.x >> 5;
    const int lane = threadIdx.x & 31;
    const int pt = blockIdx.x * 8 + warp;          // 0..8191
    const int b = pt >> 12;                         // / 4096
    const int m = pt & (MM - 1);

    // load q: channels {4*lane+j, 128+4*lane+j}
    const float4* qp = reinterpret_cast<const float4*>(fmap1 + (size_t)pt * CC);
    const float4 q0 = qp[lane];
    const float4 q1 = qp[lane + 32];

    const float cx = cents[(size_t)pt * 2 + 0];
    const float cy = cents[(size_t)pt * 2 + 1];

    const float* pyr = reinterpret_cast<const float*>(g_pyr4) + (size_t)b * BSTR;
    float* outb = out + (size_t)b * OUTCH * MM + m;

    const int lvlOff[4] = {OFF0, OFF1, OFF2, OFF3};
    const int lvlW[4]   = {64, 32, 16, 8};

    for (int lvl = 0; lvl < NLVL; lvl++) {
        const float sc = 1.0f / (float)(1 << lvl);
        const float cxl = cx * sc, cyl = cy * sc;
        const float fx0 = floorf(cxl), fy0 = floorf(cyl);
        const float wx1 = cxl - fx0, wy1 = cyl - fy0;
        const float wx0 = 1.0f - wx1, wy0 = 1.0f - wy1;
        const int gx0 = (int)fx0 - RAD;
        const int gy0 = (int)fy0 - RAD;
        const int W = lvlW[lvl];
        const float* base = pyr + lvlOff[lvl];

        // 100 lattice pixels, 2 per iteration for MLP
        for (int p = 0; p < 100; p += 2) {
            const int u0 = p % 10,       v0 = p / 10;
            const int u1 = (p + 1) % 10, v1 = (p + 1) / 10;
            const int xA = gx0 + u0, yA = gy0 + v0;
            const int xB = gx0 + u1, yB = gy0 + v1;
            const bool okA = (xA >= 0) & (xA < W) & (yA >= 0) & (yA < W);
            const bool okB = (xB >= 0) & (xB < W) & (yB >= 0) & (yB < W);
            float4 a0 = make_float4(0.f, 0.f, 0.f, 0.f), b0 = a0;
            float4 a1 = a0, b1 = a0;
            if (okA) {
                const float4* f = reinterpret_cast<const float4*>(
                    base + (((size_t)yA * W + xA) << 8));
                a0 = f[lane]; b0 = f[lane + 32];
            }
            if (okB) {
                const float4* f = reinterpret_cast<const float4*>(
                    base + (((size_t)yB * W + xB) << 8));
                a1 = f[lane]; b1 = f[lane + 32];
            }
            float s0 = a0.x * q0.x + a0.y * q0.y + a0.z * q0.z + a0.w * q0.w
                     + b0.x * q1.x + b0.y * q1.y + b0.z * q1.z + b0.w * q1.w;
            float s1 = a1.x * q0.x + a1.y * q0.y + a1.z * q0.z + a1.w * q0.w
                     + b1.x * q1.x + b1.y * q1.y + b1.z * q1.z + b1.w * q1.w;
            #pragma unroll
            for (int o = 16; o; o >>= 1) {
                s0 += __shfl_xor_sync(0xffffffffu, s0, o);
                s1 += __shfl_xor_sync(0xffffffffu, s1, o);
            }
            if (lane == 0) { Cs[warp][p] = s0; Cs[warp][p + 1] = s1; }
        }
        __syncwarp();

        const float* C = Cs[warp];
        for (int t = lane; t < SIDE * SIDE; t += 32) {
            const int i = t / 9;   // x-offset index (u = i, i+1)
            const int j = t % 9;   // y-offset index (v = j, j+1)
            const float v = wy0 * (wx0 * C[j * 10 + i] + wx1 * C[j * 10 + i + 1])
                          + wy1 * (wx0 * C[(j + 1) * 10 + i] + wx1 * C[(j + 1) * 10 + i + 1]);
            outb[(size_t)(lvl * (SIDE * SIDE) + t) * MM] = v;
        }
        __syncwarp();
    }
}

// ---------------------------------------------------------------------------
extern "C" void kernel_launch(void* const* d_in, const int* in_sizes, int n_in,
                              void* d_out, int out_size) {
    const float* fmap1 = (const float*)d_in[0];   // (B, M, C)
    const float* fmap2 = (const float*)d_in[1];   // (B, C, H, W)
    const float* cents = (const float*)d_in[2];   // (B, M, 2)
    float* out = (float*)d_out;                   // (B, 324, M)

    // Level 0: transpose to pixel-major
    {
        dim3 grid(HH * WW / 32, CC / 32, BB);
        dim3 block(32, 8);
        transpose_l0_kernel<<<grid, block>>>(fmap2);
    }
    // Levels 1..3: iterative 2x2 average pooling (pixel-major)
    {
        int tot1 = BB * 32 * 32 * CC;
        pool_kernel<<<(tot1 + 255) / 256, 256>>>(OFF0, OFF1, 64, 32, tot1);
        int tot2 = BB * 16 * 16 * CC;
        pool_kernel<<<(tot2 + 255) / 256, 256>>>(OFF1, OFF2, 32, 16, tot2);
        int tot3 = BB * 8 * 8 * CC;
        pool_kernel<<<(tot3 + 255) / 256, 256>>>(OFF2, OFF3, 16, 8, tot3);
    }
    // Fused per-point correlation + bilinear sampling
    {
        int nblocks = (BB * MM) / 8;   // 1024 blocks, warp per point
        sample_kernel<<<nblocks, 256>>>(fmap1, cents, out);
    }
}